// round 16
// baseline (speedup 1.0000x reference)
#include <cuda_runtime.h>
#include <cuda_fp16.h>
#include <math.h>
#include <stdint.h>
#include <stddef.h>

#define Bb 32
#define Tt 512
#define Dd 256
#define Hh 1024
#define G4 4096
#define BT (Bb*Tt)          // 16384
#define NCTA 128

// ---------------- scratch (device globals; no allocation allowed) ----------------
__device__ float g_xg[(size_t)BT * G4];       // 256 MB
__device__ float g_hseq[(size_t)BT * Hh];     // 64 MB (layer-1 output, fp32)
__device__ __half g_hseq16[(size_t)BT * Hh];  // 32 MB (layer-0 output, fp16)
__device__ __half g_h16[2 * 32768];           // h double buffer, fp16, paired B-frag layout
__device__ unsigned g_wf0[(size_t)NCTA * 16384];  // W_hh0 fp16 A-frags
__device__ unsigned g_wf1[(size_t)NCTA * 16384];
__device__ __half g_w16ih0[(size_t)G4 * Dd];  // fp16 weights for GEMMs
__device__ __half g_w16ih1[(size_t)G4 * Hh];
__device__ __half g_w16lin[(size_t)Hh * Hh];
__device__ unsigned int g_cnt;                // grid barrier counter

#define PQ 1152                              // partial stride: 32 rows * 36
#define SCAN_SMEM ((8*PQ + 1024 + 8*33 + 32) * 4)
#define ACH 1280

// ---------------- helpers ----------------
__device__ __forceinline__ float sigm(float x) { return 1.f / (1.f + expf(-x)); }
__device__ __forceinline__ float gelu_exact(float x) {
    return 0.5f * x * (1.f + erff(x * 0.70710678118654752440f));
}
__device__ __forceinline__ void mma_f16(float c[4], const unsigned a[4],
                                        unsigned b0, unsigned b1) {
    asm("mma.sync.aligned.m16n8k16.row.col.f32.f16.f16.f32 "
        "{%0,%1,%2,%3},{%4,%5,%6,%7},{%8,%9},{%0,%1,%2,%3};"
        : "+f"(c[0]), "+f"(c[1]), "+f"(c[2]), "+f"(c[3])
        : "r"(a[0]), "r"(a[1]), "r"(a[2]), "r"(a[3]), "r"(b0), "r"(b1));
}
__device__ __forceinline__ unsigned pack_h2(float a, float b) {
    __half2 h = __floats2half2_rn(a, b);
    return *(unsigned*)&h;
}

// ---------------- prep: W_hh[4H][H] -> per-CTA fp16 m16n8k16 A-fragment layout ----------------
__global__ void prep_whh_f16(const float* __restrict__ W, unsigned* __restrict__ out) {
    int idx = blockIdx.x * 256 + threadIdx.x;
    int lane = idx & 31;
    int j    = (idx >> 5) & 3;
    int mt   = (idx >> 7) & 1;
    int kc   = (idx >> 8) & 7;
    int kg   = (idx >> 11) & 7;
    int c    = idx >> 14;
    int rl = mt*16 + (lane >> 2) + ((j & 1) << 3);
    int R  = (rl >> 3) * 1024 + c*8 + (rl & 7);
    int k0 = kg*128 + kc*16 + ((j >> 1) << 3) + ((lane & 3) << 1);
    out[idx] = pack_h2(W[(size_t)R * Hh + k0], W[(size_t)R * Hh + k0 + 1]);
}

// ---------------- prep: fp32 weights -> fp16 ----------------
__global__ void prep_w16(const float* __restrict__ W, __half* __restrict__ out, int n2) {
    int i = blockIdx.x * 256 + threadIdx.x;
    if (i < n2) {
        float2 v = ((const float2*)W)[i];
        ((__half2*)out)[i] = __floats2half2_rn(v.x, v.y);
    }
}

// ---------------- reset ----------------
__global__ void reset_scan_state() {
    int i = blockIdx.x * blockDim.x + threadIdx.x;
    if (i == 0) g_cnt = 0u;
    for (int j = i; j < 2 * 32768 / 2; j += gridDim.x * blockDim.x)
        ((__half2*)g_h16)[j] = __half2half2(__float2half(0.f));
}

// ---------------- fp16 GEMM (m16n8k16), fragment-native smem, 2 CTAs/SM ----------------
template <typename AT>
__global__ void __launch_bounds__(256, 2) gemm_f16_nt_bias(
    const AT* __restrict__ A, const __half* __restrict__ Bw,
    const float* __restrict__ b1, const float* __restrict__ b2,
    float* __restrict__ C, int M, int N, int K)
{
    __shared__ unsigned As[2][ACH];
    __shared__ unsigned Bs[2][ACH];

    const int tid  = threadIdx.x;
    const int lane = tid & 31;
    const int wid  = tid >> 5;
    const int bm   = blockIdx.y << 7;
    const int bn   = blockIdx.x << 7;
    const int wm   = (wid >> 2) << 6;
    const int wn   = (wid & 3) << 5;
    const int lr   = lane >> 2;
    const int lc   = lane & 3;

    const int mrow = tid >> 1;
    const int kk8  = tid & 1;

    const int a_off = (mrow >> 4)*160 + (((mrow >> 3) & 1) + 2*kk8)*40 + (mrow & 7)*4;
    const int b_off = (mrow >> 3)*80 + kk8*40 + (mrow & 7)*4;

    const AT*     Ap = A + (size_t)(bm + mrow) * K + kk8*8;
    const __half* Bp = Bw + (size_t)(bn + mrow) * K + kk8*8;

    float acc[4][4][4];
#pragma unroll
    for (int mt = 0; mt < 4; mt++)
#pragma unroll
        for (int nt = 0; nt < 4; nt++)
#pragma unroll
            for (int j = 0; j < 4; j++) acc[mt][nt][j] = 0.f;

    const int NC = K >> 4;
    uint4 apk, bpk;

    if constexpr (sizeof(AT) == 2) {
        apk = *(const uint4*)Ap;
    } else {
        float4 ra0 = *(const float4*)(Ap + 0);
        float4 ra1 = *(const float4*)(Ap + 4);
        apk = make_uint4(pack_h2(ra0.x, ra0.y), pack_h2(ra0.z, ra0.w),
                         pack_h2(ra1.x, ra1.y), pack_h2(ra1.z, ra1.w));
    }
    bpk = *(const uint4*)Bp;
    {
        unsigned* as = &As[0][0]; unsigned* bs = &Bs[0][0];
        *(uint4*)(as + a_off) = apk;
        *(uint4*)(bs + b_off) = bpk;
    }
    __syncthreads();

    for (int c = 0; c < NC; c++) {
        const int p = c & 1;
        if (c + 1 < NC) {
            const AT*     Apn = Ap + (size_t)(c + 1) * 16;
            const __half* Bpn = Bp + (size_t)(c + 1) * 16;
            if constexpr (sizeof(AT) == 2) {
                apk = *(const uint4*)Apn;
            } else {
                float4 ra0 = *(const float4*)(Apn + 0);
                float4 ra1 = *(const float4*)(Apn + 4);
                apk = make_uint4(pack_h2(ra0.x, ra0.y), pack_h2(ra0.z, ra0.w),
                                 pack_h2(ra1.x, ra1.y), pack_h2(ra1.z, ra1.w));
            }
            bpk = *(const uint4*)Bpn;
        }

        const unsigned* as = &As[p][0];
        const unsigned* bs = &Bs[p][0];

        unsigned Af[4][4];
#pragma unroll
        for (int mt = 0; mt < 4; mt++) {
            const unsigned* ap = as + ((wm >> 4) + mt)*160 + lane;
            Af[mt][0] = ap[0];
            Af[mt][1] = ap[40];
            Af[mt][2] = ap[80];
            Af[mt][3] = ap[120];
        }
        unsigned Bf[4][2];
#pragma unroll
        for (int nt = 0; nt < 4; nt++) {
            const unsigned* bp = bs + ((wn >> 3) + nt)*80 + lane;
            Bf[nt][0] = bp[0];
            Bf[nt][1] = bp[40];
        }
#pragma unroll
        for (int mt = 0; mt < 4; mt++)
#pragma unroll
            for (int nt = 0; nt < 4; nt++)
                mma_f16(acc[mt][nt], Af[mt], Bf[nt][0], Bf[nt][1]);

        if (c + 1 < NC) {
            unsigned* asn = &As[1 - p][0]; unsigned* bsn = &Bs[1 - p][0];
            *(uint4*)(asn + a_off) = apk;
            *(uint4*)(bsn + b_off) = bpk;
            __syncthreads();
        }
    }

#pragma unroll
    for (int nt = 0; nt < 4; nt++) {
        int col = bn + wn + nt*8 + lc*2;
        float bb0 = b1[col]     + (b2 ? b2[col]     : 0.f);
        float bb1 = b1[col + 1] + (b2 ? b2[col + 1] : 0.f);
#pragma unroll
        for (int mt = 0; mt < 4; mt++) {
            int row = bm + wm + mt*16 + lr;
            float2 v0 = make_float2(acc[mt][nt][0] + bb0, acc[mt][nt][1] + bb1);
            float2 v1 = make_float2(acc[mt][nt][2] + bb0, acc[mt][nt][3] + bb1);
            *(float2*)(C + (size_t)row * N + col)       = v0;
            *(float2*)(C + (size_t)(row + 8) * N + col) = v1;
        }
    }
}

// ---------------- persistent LSTM scan: paired-fragment h layout (LDG.64 loads) ----------------
// h16 uint index: (kcg*32 + n)*8 + l4*2 + hh   (hh = B-frag half; pairs adjacent)
// Per-(kc,nt) warp load: uint2 at uint index 2*(kcg*128 + nt*32 + lane) -> 256B coalesced.
// OT = __half (layer 0) or float (layer 1).
template <typename OT>
__global__ void __launch_bounds__(256, 1) lstm_scan(
    const unsigned* __restrict__ wf,
    const float* __restrict__ xg,
    OT* __restrict__ hseq)
{
    extern __shared__ float smem[];
    float* part = smem;                          // 8 * PQ
    float* sXG  = part + 8*PQ;                   // 1024: [b][gate][u]
    float* sHT  = sXG + 1024;                    // 8*33

    const int tid  = threadIdx.x;
    const int lane = tid & 31;
    const int kg   = tid >> 5;
    const int u0   = blockIdx.x * 8;

    unsigned wreg[8][2][4];
    {
        const unsigned* wb = wf + (size_t)blockIdx.x * 16384;
#pragma unroll
        for (int kc = 0; kc < 8; kc++)
#pragma unroll
            for (int mt = 0; mt < 2; mt++)
#pragma unroll
                for (int j = 0; j < 4; j++)
                    wreg[kc][mt][j] = wb[((kg*8 + kc)*2 + mt)*128 + j*32 + lane];
    }

    const int pb = tid >> 3;
    const int pg = (tid >> 1) & 3;
    const int ph = (tid & 1) << 2;
    const float* xg_base = xg + (size_t)pb * Tt * G4 + pg*1024 + u0 + ph;
    float4 px = *(const float4*)xg_base;

    const int uu = kg;
    const int b  = lane;
    const int lr = lane >> 2;
    const int lc = lane & 3;
    float c_state = 0.f;
    unsigned bar = 0;

    // h write slot (paired layout): half index = ((kcg*32 + b)*8 + l4*2 + hh)*2 + pos
    const int u = u0 + uu;
    const int w_kcg = u >> 4;
    const int w_hh  = (u >> 3) & 1;
    const int w_l4  = (u & 7) >> 1;
    const int w_pos = u & 1;
    const int w_idx = (((w_kcg*32 + b)*8 + w_l4*2 + w_hh) << 1) + w_pos;

    for (int t = 0; t < Tt; t++) {
        {
            float* d = sXG + pb*32 + pg*8 + ph;
            d[0] = px.x; d[1] = px.y; d[2] = px.z; d[3] = px.w;
            int tn = (t + 1 < Tt) ? (t + 1) : t;
            px = *(const float4*)(xg_base + (size_t)tn * G4);
        }

        const int rp = t & 1;
        const uint2* hb2 = (const uint2*)((const unsigned*)g_h16 + rp * 16384);

        // 32 coalesced LDG.64 per thread (paired fragment halves)
        uint2 hq[8][4];
#pragma unroll
        for (int kc = 0; kc < 8; kc++) {
            const int kcg = kg*8 + kc;
#pragma unroll
            for (int nt = 0; nt < 4; nt++)
                hq[kc][nt] = __ldcg(hb2 + kcg*128 + nt*32 + lane);
        }

        float acc[2][4][4];
#pragma unroll
        for (int mt = 0; mt < 2; mt++)
#pragma unroll
            for (int nt = 0; nt < 4; nt++)
#pragma unroll
                for (int j = 0; j < 4; j++) acc[mt][nt][j] = 0.f;

#pragma unroll
        for (int kc = 0; kc < 8; kc++) {
#pragma unroll
            for (int nt = 0; nt < 4; nt++) {
                mma_f16(acc[0][nt], wreg[kc][0], hq[kc][nt].x, hq[kc][nt].y);
                mma_f16(acc[1][nt], wreg[kc][1], hq[kc][nt].x, hq[kc][nt].y);
            }
        }

#pragma unroll
        for (int mt = 0; mt < 2; mt++)
#pragma unroll
            for (int jh = 0; jh < 2; jh++) {
                int r = mt*16 + jh*8 + lr;
#pragma unroll
                for (int nt = 0; nt < 4; nt++) {
                    int n = nt*8 + lc*2;
                    *(float2*)(part + kg*PQ + r*36 + n) =
                        make_float2(acc[mt][nt][jh*2 + 0], acc[mt][nt][jh*2 + 1]);
                }
            }
        __syncthreads();

        float ga[4];
#pragma unroll
        for (int g = 0; g < 4; g++) {
            int roff = (g*8 + uu)*36 + b;
            float s = 0.f;
#pragma unroll
            for (int q = 0; q < 8; q++) s += part[q*PQ + roff];
            ga[g] = s + sXG[b*32 + g*8 + uu];
        }
        float ig = sigm(ga[0]);
        float fg = sigm(ga[1]);
        float gg = tanhf(ga[2]);
        float og = sigm(ga[3]);
        c_state = fg * c_state + ig * gg;
        float hval = og * tanhf(c_state);

        g_h16[(1 - rp)*32768 + w_idx] = __float2half_rn(hval);
        sHT[uu*33 + b] = hval;
        __syncthreads();

        {
            int b_ = tid >> 3, uo = tid & 7;
            hseq[((size_t)b_ * Tt + t) * Hh + u0 + uo] = (OT)sHT[uo*33 + b_];
        }

        if (tid == 0) {
            __threadfence();
            atomicAdd(&g_cnt, 1u);
            bar += NCTA;
            while (*((volatile unsigned int*)&g_cnt) < bar) { __nanosleep(40); }
            __threadfence();
        }
        __syncthreads();
    }
}

// ---------------- LayerNorm -> GELU ----------------
__global__ void ln_gelu_kernel(const float* __restrict__ X, const float* __restrict__ w,
                               const float* __restrict__ bv, float* __restrict__ Y)
{
    __shared__ float red[2][8];
    const int row = blockIdx.x;
    const int tid = threadIdx.x;
    float4 v = ((const float4*)(X + (size_t)row * Hh))[tid];
    float s = v.x + v.y + v.z + v.w;
    float q = v.x*v.x + v.y*v.y + v.z*v.z + v.w*v.w;
    int lane = tid & 31, wid = tid >> 5;
#pragma unroll
    for (int o = 16; o; o >>= 1) {
        s += __shfl_xor_sync(0xffffffffu, s, o);
        q += __shfl_xor_sync(0xffffffffu, q, o);
    }
    if (lane == 0) { red[0][wid] = s; red[1][wid] = q; }
    __syncthreads();
    if (wid == 0) {
        s = (lane < 8) ? red[0][lane] : 0.f;
        q = (lane < 8) ? red[1][lane] : 0.f;
#pragma unroll
        for (int o = 4; o; o >>= 1) {
            s += __shfl_xor_sync(0xffffffffu, s, o);
            q += __shfl_xor_sync(0xffffffffu, q, o);
        }
        if (lane == 0) { red[0][0] = s; red[1][0] = q; }
    }
    __syncthreads();
    float mu  = red[0][0] * (1.f / Hh);
    float var = red[1][0] * (1.f / Hh) - mu * mu;
    float rstd = rsqrtf(var + 1e-5f);
    float4 wv = ((const float4*)w)[tid];
    float4 bb = ((const float4*)bv)[tid];
    float4 y;
    y.x = gelu_exact((v.x - mu) * rstd * wv.x + bb.x);
    y.y = gelu_exact((v.y - mu) * rstd * wv.y + bb.y);
    y.z = gelu_exact((v.z - mu) * rstd * wv.z + bb.z);
    y.w = gelu_exact((v.w - mu) * rstd * wv.w + bb.w);
    ((float4*)(Y + (size_t)row * Hh))[tid] = y;
}

// ---------------- GELU -> LayerNorm ----------------
__global__ void gelu_ln_kernel(const float* __restrict__ X, const float* __restrict__ w,
                               const float* __restrict__ bv, float* __restrict__ Y)
{
    __shared__ float red[2][8];
    const int row = blockIdx.x;
    const int tid = threadIdx.x;
    float4 v = ((const float4*)(X + (size_t)row * Hh))[tid];
    v.x = gelu_exact(v.x); v.y = gelu_exact(v.y);
    v.z = gelu_exact(v.z); v.w = gelu_exact(v.w);
    float s = v.x + v.y + v.z + v.w;
    float q = v.x*v.x + v.y*v.y + v.z*v.z + v.w*v.w;
    int lane = tid & 31, wid = tid >> 5;
#pragma unroll
    for (int o = 16; o; o >>= 1) {
        s += __shfl_xor_sync(0xffffffffu, s, o);
        q += __shfl_xor_sync(0xffffffffu, q, o);
    }
    if (lane == 0) { red[0][wid] = s; red[1][wid] = q; }
    __syncthreads();
    if (wid == 0) {
        s = (lane < 8) ? red[0][lane] : 0.f;
        q = (lane < 8) ? red[1][lane] : 0.f;
#pragma unroll
        for (int o = 4; o; o >>= 1) {
            s += __shfl_xor_sync(0xffffffffu, s, o);
            q += __shfl_xor_sync(0xffffffffu, q, o);
        }
        if (lane == 0) { red[0][0] = s; red[1][0] = q; }
    }
    __syncthreads();
    float mu  = red[0][0] * (1.f / Hh);
    float var = red[1][0] * (1.f / Hh) - mu * mu;
    float rstd = rsqrtf(var + 1e-5f);
    float4 wv = ((const float4*)w)[tid];
    float4 bb = ((const float4*)bv)[tid];
    float4 y;
    y.x = (v.x - mu) * rstd * wv.x + bb.x;
    y.y = (v.y - mu) * rstd * wv.y + bb.y;
    y.z = (v.z - mu) * rstd * wv.z + bb.z;
    y.w = (v.w - mu) * rstd * wv.w + bb.w;
    ((float4*)(Y + (size_t)row * Hh))[tid] = y;
}

// ---------------- driver ----------------
extern "C" void kernel_launch(void* const* d_in, const int* in_sizes, int n_in,
                              void* d_out, int out_size)
{
    const float* bone  = (const float*)d_in[0];
    const float* W_ih0 = (const float*)d_in[1];
    const float* W_hh0 = (const float*)d_in[2];
    const float* b_ih0 = (const float*)d_in[3];
    const float* b_hh0 = (const float*)d_in[4];
    const float* W_ih1 = (const float*)d_in[5];
    const float* W_hh1 = (const float*)d_in[6];
    const float* b_ih1 = (const float*)d_in[7];
    const float* b_hh1 = (const float*)d_in[8];
    const float* ln1w  = (const float*)d_in[9];
    const float* ln1b  = (const float*)d_in[10];
    const float* linw  = (const float*)d_in[11];
    const float* linb  = (const float*)d_in[12];
    const float* ln2w  = (const float*)d_in[13];
    const float* ln2b  = (const float*)d_in[14];
    float* out = (float*)d_out;

    float *xg = nullptr, *hseq = nullptr;
    __half *hseq16 = nullptr, *w16ih0 = nullptr, *w16ih1 = nullptr, *w16lin = nullptr;
    unsigned *wf0 = nullptr, *wf1 = nullptr;
    cudaGetSymbolAddress((void**)&xg, g_xg);
    cudaGetSymbolAddress((void**)&hseq, g_hseq);
    cudaGetSymbolAddress((void**)&hseq16, g_hseq16);
    cudaGetSymbolAddress((void**)&wf0, g_wf0);
    cudaGetSymbolAddress((void**)&wf1, g_wf1);
    cudaGetSymbolAddress((void**)&w16ih0, g_w16ih0);
    cudaGetSymbolAddress((void**)&w16ih1, g_w16ih1);
    cudaGetSymbolAddress((void**)&w16lin, g_w16lin);
    float* act = xg;
    float* lin = xg + (size_t)BT * Hh;

    cudaFuncSetAttribute(lstm_scan<__half>, cudaFuncAttributeMaxDynamicSharedMemorySize, SCAN_SMEM);
    cudaFuncSetAttribute(lstm_scan<float>,  cudaFuncAttributeMaxDynamicSharedMemorySize, SCAN_SMEM);

    dim3 gemm_g4(G4/128, BT/128);
    dim3 gemm_h(Hh/128, BT/128);

    // weight preps (per launch; ~tens of µs total)
    prep_whh_f16<<<8192, 256>>>(W_hh0, wf0);
    prep_whh_f16<<<8192, 256>>>(W_hh1, wf1);
    prep_w16<<<(G4*Dd/2 + 255)/256, 256>>>(W_ih0, w16ih0, G4*Dd/2);
    prep_w16<<<(G4*Hh/2 + 255)/256, 256>>>(W_ih1, w16ih1, G4*Hh/2);
    prep_w16<<<(Hh*Hh/2 + 255)/256, 256>>>(linw,  w16lin, Hh*Hh/2);

    // layer 0: gates from fp32 input; scan writes fp16 hseq
    gemm_f16_nt_bias<float><<<gemm_g4, 256>>>(bone, w16ih0, b_ih0, b_hh0, xg, BT, G4, Dd);
    reset_scan_state<<<64, 256>>>();
    lstm_scan<__half><<<NCTA, 256, SCAN_SMEM>>>(wf0, xg, hseq16);

    // layer 1: gates from fp16 hseq (A-half GEMM); scan writes fp32 hseq
    gemm_f16_nt_bias<__half><<<gemm_g4, 256>>>(hseq16, w16ih1, b_ih1, b_hh1, xg, BT, G4, Hh);
    reset_scan_state<<<64, 256>>>();
    lstm_scan<float><<<NCTA, 256, SCAN_SMEM>>>(wf1, xg, hseq);

    // post: LN -> GELU -> Linear -> GELU -> LN
    ln_gelu_kernel<<<BT, 256>>>(hseq, ln1w, ln1b, act);
    gemm_f16_nt_bias<float><<<gemm_h, 256>>>(act, w16lin, linb, nullptr, lin, BT, Hh, Hh);
    gelu_ln_kernel<<<BT, 256>>>(lin, ln2w, ln2b, out);
}

// round 17
// speedup vs baseline: 1.0133x; 1.0133x over previous
#include <cuda_runtime.h>
#include <cuda_fp16.h>
#include <math.h>
#include <stdint.h>
#include <stddef.h>

#define Bb 32
#define Tt 512
#define Dd 256
#define Hh 1024
#define G4 4096
#define BT (Bb*Tt)          // 16384
#define NCTA 128

// ---------------- scratch (device globals; no allocation allowed) ----------------
__device__ float g_xg[(size_t)BT * G4];       // 256 MB
__device__ float g_hseq[(size_t)BT * Hh];     // 64 MB (layer-1 output, fp32)
__device__ __half g_hseq16[(size_t)BT * Hh];  // 32 MB (layer-0 output, fp16)
__device__ __half g_act16[(size_t)BT * Hh];   // 32 MB (post-LN/GELU activations, fp16)
__device__ __half g_h16[2 * 32768];           // h double buffer, fp16, paired B-frag layout
__device__ unsigned g_wf0[(size_t)NCTA * 16384];  // W_hh0 fp16 A-frags
__device__ unsigned g_wf1[(size_t)NCTA * 16384];
__device__ __half g_w16ih0[(size_t)G4 * Dd];  // fp16 weights for GEMMs
__device__ __half g_w16ih1[(size_t)G4 * Hh];
__device__ __half g_w16lin[(size_t)Hh * Hh];
__device__ unsigned int g_cnt;                // grid barrier counter

#define PQ 1152                              // partial stride: 32 rows * 36
#define SCAN_SMEM ((8*PQ + 1024 + 8*33 + 32) * 4)
#define ACH 1280

// ---------------- helpers ----------------
__device__ __forceinline__ float sigm(float x) { return 1.f / (1.f + expf(-x)); }
__device__ __forceinline__ float gelu_exact(float x) {
    return 0.5f * x * (1.f + erff(x * 0.70710678118654752440f));
}
__device__ __forceinline__ void mma_f16(float c[4], const unsigned a[4],
                                        unsigned b0, unsigned b1) {
    asm("mma.sync.aligned.m16n8k16.row.col.f32.f16.f16.f32 "
        "{%0,%1,%2,%3},{%4,%5,%6,%7},{%8,%9},{%0,%1,%2,%3};"
        : "+f"(c[0]), "+f"(c[1]), "+f"(c[2]), "+f"(c[3])
        : "r"(a[0]), "r"(a[1]), "r"(a[2]), "r"(a[3]), "r"(b0), "r"(b1));
}
__device__ __forceinline__ unsigned pack_h2(float a, float b) {
    __half2 h = __floats2half2_rn(a, b);
    return *(unsigned*)&h;
}

// ---------------- prep: both W_hh -> per-CTA fp16 A-fragment layouts (one launch) ----------------
__global__ void prep_whh_f16_2(const float* __restrict__ W0, unsigned* __restrict__ out0,
                               const float* __restrict__ W1, unsigned* __restrict__ out1) {
    int gidx = blockIdx.x * 256 + threadIdx.x;   // 4,194,304 total
    const float* W = (gidx < 2097152) ? W0 : W1;
    unsigned* out  = (gidx < 2097152) ? out0 : out1;
    int idx = gidx & 2097151;
    int lane = idx & 31;
    int j    = (idx >> 5) & 3;
    int mt   = (idx >> 7) & 1;
    int kc   = (idx >> 8) & 7;
    int kg   = (idx >> 11) & 7;
    int c    = idx >> 14;
    int rl = mt*16 + (lane >> 2) + ((j & 1) << 3);
    int R  = (rl >> 3) * 1024 + c*8 + (rl & 7);
    int k0 = kg*128 + kc*16 + ((j >> 1) << 3) + ((lane & 3) << 1);
    out[idx] = pack_h2(W[(size_t)R * Hh + k0], W[(size_t)R * Hh + k0 + 1]);
}

// ---------------- prep: all three fp32 weight mats -> fp16 (one launch) ----------------
#define N2_IH0 (G4*Dd/2)            // 524288
#define N2_IH1 (G4*Hh/2)            // 2097152
#define N2_LIN (Hh*Hh/2)            // 524288
__global__ void prep_w16_all(const float* __restrict__ Wih0, __half* __restrict__ o0,
                             const float* __restrict__ Wih1, __half* __restrict__ o1,
                             const float* __restrict__ Wlin, __half* __restrict__ o2) {
    int i = blockIdx.x * 256 + threadIdx.x;      // 3,145,728 total
    const float* W; __half* o; int k;
    if (i < N2_IH0)                { W = Wih0; o = o0; k = i; }
    else if (i < N2_IH0 + N2_IH1)  { W = Wih1; o = o1; k = i - N2_IH0; }
    else                           { W = Wlin; o = o2; k = i - N2_IH0 - N2_IH1; }
    float2 v = ((const float2*)W)[k];
    ((__half2*)o)[k] = __floats2half2_rn(v.x, v.y);
}

// ---------------- reset ----------------
__global__ void reset_scan_state() {
    int i = blockIdx.x * blockDim.x + threadIdx.x;
    if (i == 0) g_cnt = 0u;
    for (int j = i; j < 2 * 32768 / 2; j += gridDim.x * blockDim.x)
        ((__half2*)g_h16)[j] = __half2half2(__float2half(0.f));
}

// ---------------- fp16 GEMM (m16n8k16), fragment-native smem, 2 CTAs/SM ----------------
template <typename AT>
__global__ void __launch_bounds__(256, 2) gemm_f16_nt_bias(
    const AT* __restrict__ A, const __half* __restrict__ Bw,
    const float* __restrict__ b1, const float* __restrict__ b2,
    float* __restrict__ C, int M, int N, int K)
{
    __shared__ unsigned As[2][ACH];
    __shared__ unsigned Bs[2][ACH];

    const int tid  = threadIdx.x;
    const int lane = tid & 31;
    const int wid  = tid >> 5;
    const int bm   = blockIdx.y << 7;
    const int bn   = blockIdx.x << 7;
    const int wm   = (wid >> 2) << 6;
    const int wn   = (wid & 3) << 5;
    const int lr   = lane >> 2;
    const int lc   = lane & 3;

    const int mrow = tid >> 1;
    const int kk8  = tid & 1;

    const int a_off = (mrow >> 4)*160 + (((mrow >> 3) & 1) + 2*kk8)*40 + (mrow & 7)*4;
    const int b_off = (mrow >> 3)*80 + kk8*40 + (mrow & 7)*4;

    const AT*     Ap = A + (size_t)(bm + mrow) * K + kk8*8;
    const __half* Bp = Bw + (size_t)(bn + mrow) * K + kk8*8;

    float acc[4][4][4];
#pragma unroll
    for (int mt = 0; mt < 4; mt++)
#pragma unroll
        for (int nt = 0; nt < 4; nt++)
#pragma unroll
            for (int j = 0; j < 4; j++) acc[mt][nt][j] = 0.f;

    const int NC = K >> 4;
    uint4 apk, bpk;

    if constexpr (sizeof(AT) == 2) {
        apk = *(const uint4*)Ap;
    } else {
        float4 ra0 = *(const float4*)(Ap + 0);
        float4 ra1 = *(const float4*)(Ap + 4);
        apk = make_uint4(pack_h2(ra0.x, ra0.y), pack_h2(ra0.z, ra0.w),
                         pack_h2(ra1.x, ra1.y), pack_h2(ra1.z, ra1.w));
    }
    bpk = *(const uint4*)Bp;
    {
        unsigned* as = &As[0][0]; unsigned* bs = &Bs[0][0];
        *(uint4*)(as + a_off) = apk;
        *(uint4*)(bs + b_off) = bpk;
    }
    __syncthreads();

    for (int c = 0; c < NC; c++) {
        const int p = c & 1;
        if (c + 1 < NC) {
            const AT*     Apn = Ap + (size_t)(c + 1) * 16;
            const __half* Bpn = Bp + (size_t)(c + 1) * 16;
            if constexpr (sizeof(AT) == 2) {
                apk = *(const uint4*)Apn;
            } else {
                float4 ra0 = *(const float4*)(Apn + 0);
                float4 ra1 = *(const float4*)(Apn + 4);
                apk = make_uint4(pack_h2(ra0.x, ra0.y), pack_h2(ra0.z, ra0.w),
                                 pack_h2(ra1.x, ra1.y), pack_h2(ra1.z, ra1.w));
            }
            bpk = *(const uint4*)Bpn;
        }

        const unsigned* as = &As[p][0];
        const unsigned* bs = &Bs[p][0];

        unsigned Af[4][4];
#pragma unroll
        for (int mt = 0; mt < 4; mt++) {
            const unsigned* ap = as + ((wm >> 4) + mt)*160 + lane;
            Af[mt][0] = ap[0];
            Af[mt][1] = ap[40];
            Af[mt][2] = ap[80];
            Af[mt][3] = ap[120];
        }
        unsigned Bf[4][2];
#pragma unroll
        for (int nt = 0; nt < 4; nt++) {
            const unsigned* bp = bs + ((wn >> 3) + nt)*80 + lane;
            Bf[nt][0] = bp[0];
            Bf[nt][1] = bp[40];
        }
#pragma unroll
        for (int mt = 0; mt < 4; mt++)
#pragma unroll
            for (int nt = 0; nt < 4; nt++)
                mma_f16(acc[mt][nt], Af[mt], Bf[nt][0], Bf[nt][1]);

        if (c + 1 < NC) {
            unsigned* asn = &As[1 - p][0]; unsigned* bsn = &Bs[1 - p][0];
            *(uint4*)(asn + a_off) = apk;
            *(uint4*)(bsn + b_off) = bpk;
            __syncthreads();
        }
    }

#pragma unroll
    for (int nt = 0; nt < 4; nt++) {
        int col = bn + wn + nt*8 + lc*2;
        float bb0 = b1[col]     + (b2 ? b2[col]     : 0.f);
        float bb1 = b1[col + 1] + (b2 ? b2[col + 1] : 0.f);
#pragma unroll
        for (int mt = 0; mt < 4; mt++) {
            int row = bm + wm + mt*16 + lr;
            float2 v0 = make_float2(acc[mt][nt][0] + bb0, acc[mt][nt][1] + bb1);
            float2 v1 = make_float2(acc[mt][nt][2] + bb0, acc[mt][nt][3] + bb1);
            *(float2*)(C + (size_t)row * N + col)       = v0;
            *(float2*)(C + (size_t)(row + 8) * N + col) = v1;
        }
    }
}

// ---------------- persistent LSTM scan (R16 structure; 20ns poll backoff) ----------------
// OT = __half (layer 0) or float (layer 1).
template <typename OT>
__global__ void __launch_bounds__(256, 1) lstm_scan(
    const unsigned* __restrict__ wf,
    const float* __restrict__ xg,
    OT* __restrict__ hseq)
{
    extern __shared__ float smem[];
    float* part = smem;                          // 8 * PQ
    float* sXG  = part + 8*PQ;                   // 1024: [b][gate][u]
    float* sHT  = sXG + 1024;                    // 8*33

    const int tid  = threadIdx.x;
    const int lane = tid & 31;
    const int kg   = tid >> 5;
    const int u0   = blockIdx.x * 8;

    unsigned wreg[8][2][4];
    {
        const unsigned* wb = wf + (size_t)blockIdx.x * 16384;
#pragma unroll
        for (int kc = 0; kc < 8; kc++)
#pragma unroll
            for (int mt = 0; mt < 2; mt++)
#pragma unroll
                for (int j = 0; j < 4; j++)
                    wreg[kc][mt][j] = wb[((kg*8 + kc)*2 + mt)*128 + j*32 + lane];
    }

    const int pb = tid >> 3;
    const int pg = (tid >> 1) & 3;
    const int ph = (tid & 1) << 2;
    const float* xg_base = xg + (size_t)pb * Tt * G4 + pg*1024 + u0 + ph;
    float4 px = *(const float4*)xg_base;

    const int uu = kg;
    const int b  = lane;
    const int lr = lane >> 2;
    const int lc = lane & 3;
    float c_state = 0.f;
    unsigned bar = 0;

    const int u = u0 + uu;
    const int w_kcg = u >> 4;
    const int w_hh  = (u >> 3) & 1;
    const int w_l4  = (u & 7) >> 1;
    const int w_pos = u & 1;
    const int w_idx = (((w_kcg*32 + b)*8 + w_l4*2 + w_hh) << 1) + w_pos;

    for (int t = 0; t < Tt; t++) {
        {
            float* d = sXG + pb*32 + pg*8 + ph;
            d[0] = px.x; d[1] = px.y; d[2] = px.z; d[3] = px.w;
            int tn = (t + 1 < Tt) ? (t + 1) : t;
            px = *(const float4*)(xg_base + (size_t)tn * G4);
        }

        const int rp = t & 1;
        const uint2* hb2 = (const uint2*)((const unsigned*)g_h16 + rp * 16384);

        uint2 hq[8][4];
#pragma unroll
        for (int kc = 0; kc < 8; kc++) {
            const int kcg = kg*8 + kc;
#pragma unroll
            for (int nt = 0; nt < 4; nt++)
                hq[kc][nt] = __ldcg(hb2 + kcg*128 + nt*32 + lane);
        }

        float acc[2][4][4];
#pragma unroll
        for (int mt = 0; mt < 2; mt++)
#pragma unroll
            for (int nt = 0; nt < 4; nt++)
#pragma unroll
                for (int j = 0; j < 4; j++) acc[mt][nt][j] = 0.f;

#pragma unroll
        for (int kc = 0; kc < 8; kc++) {
#pragma unroll
            for (int nt = 0; nt < 4; nt++) {
                mma_f16(acc[0][nt], wreg[kc][0], hq[kc][nt].x, hq[kc][nt].y);
                mma_f16(acc[1][nt], wreg[kc][1], hq[kc][nt].x, hq[kc][nt].y);
            }
        }

#pragma unroll
        for (int mt = 0; mt < 2; mt++)
#pragma unroll
            for (int jh = 0; jh < 2; jh++) {
                int r = mt*16 + jh*8 + lr;
#pragma unroll
                for (int nt = 0; nt < 4; nt++) {
                    int n = nt*8 + lc*2;
                    *(float2*)(part + kg*PQ + r*36 + n) =
                        make_float2(acc[mt][nt][jh*2 + 0], acc[mt][nt][jh*2 + 1]);
                }
            }
        __syncthreads();

        float ga[4];
#pragma unroll
        for (int g = 0; g < 4; g++) {
            int roff = (g*8 + uu)*36 + b;
            float s = 0.f;
#pragma unroll
            for (int q = 0; q < 8; q++) s += part[q*PQ + roff];
            ga[g] = s + sXG[b*32 + g*8 + uu];
        }
        float ig = sigm(ga[0]);
        float fg = sigm(ga[1]);
        float gg = tanhf(ga[2]);
        float og = sigm(ga[3]);
        c_state = fg * c_state + ig * gg;
        float hval = og * tanhf(c_state);

        g_h16[(1 - rp)*32768 + w_idx] = __float2half_rn(hval);
        sHT[uu*33 + b] = hval;
        __syncthreads();

        {
            int b_ = tid >> 3, uo = tid & 7;
            hseq[((size_t)b_ * Tt + t) * Hh + u0 + uo] = (OT)sHT[uo*33 + b_];
        }

        if (tid == 0) {
            __threadfence();
            atomicAdd(&g_cnt, 1u);
            bar += NCTA;
            while (*((volatile unsigned int*)&g_cnt) < bar) { __nanosleep(20); }
            __threadfence();
        }
        __syncthreads();
    }
}

// ---------------- LayerNorm -> GELU (fp16 output for fp16 GEMM A path) ----------------
__global__ void ln_gelu_kernel(const float* __restrict__ X, const float* __restrict__ w,
                               const float* __restrict__ bv, __half* __restrict__ Y)
{
    __shared__ float red[2][8];
    const int row = blockIdx.x;
    const int tid = threadIdx.x;
    float4 v = ((const float4*)(X + (size_t)row * Hh))[tid];
    float s = v.x + v.y + v.z + v.w;
    float q = v.x*v.x + v.y*v.y + v.z*v.z + v.w*v.w;
    int lane = tid & 31, wid = tid >> 5;
#pragma unroll
    for (int o = 16; o; o >>= 1) {
        s += __shfl_xor_sync(0xffffffffu, s, o);
        q += __shfl_xor_sync(0xffffffffu, q, o);
    }
    if (lane == 0) { red[0][wid] = s; red[1][wid] = q; }
    __syncthreads();
    if (wid == 0) {
        s = (lane < 8) ? red[0][lane] : 0.f;
        q = (lane < 8) ? red[1][lane] : 0.f;
#pragma unroll
        for (int o = 4; o; o >>= 1) {
            s += __shfl_xor_sync(0xffffffffu, s, o);
            q += __shfl_xor_sync(0xffffffffu, q, o);
        }
        if (lane == 0) { red[0][0] = s; red[1][0] = q; }
    }
    __syncthreads();
    float mu  = red[0][0] * (1.f / Hh);
    float var = red[1][0] * (1.f / Hh) - mu * mu;
    float rstd = rsqrtf(var + 1e-5f);
    float4 wv = ((const float4*)w)[tid];
    float4 bb = ((const float4*)bv)[tid];
    float y0 = gelu_exact((v.x - mu) * rstd * wv.x + bb.x);
    float y1 = gelu_exact((v.y - mu) * rstd * wv.y + bb.y);
    float y2 = gelu_exact((v.z - mu) * rstd * wv.z + bb.z);
    float y3 = gelu_exact((v.w - mu) * rstd * wv.w + bb.w);
    __half2* yp = (__half2*)(Y + (size_t)row * Hh) + tid*2;
    yp[0] = __floats2half2_rn(y0, y1);
    yp[1] = __floats2half2_rn(y2, y3);
}

// ---------------- GELU -> LayerNorm ----------------
__global__ void gelu_ln_kernel(const float* __restrict__ X, const float* __restrict__ w,
                               const float* __restrict__ bv, float* __restrict__ Y)
{
    __shared__ float red[2][8];
    const int row = blockIdx.x;
    const int tid = threadIdx.x;
    float4 v = ((const float4*)(X + (size_t)row * Hh))[tid];
    v.x = gelu_exact(v.x); v.y = gelu_exact(v.y);
    v.z = gelu_exact(v.z); v.w = gelu_exact(v.w);
    float s = v.x + v.y + v.z + v.w;
    float q = v.x*v.x + v.y*v.y + v.z*v.z + v.w*v.w;
    int lane = tid & 31, wid = tid >> 5;
#pragma unroll
    for (int o = 16; o; o >>= 1) {
        s += __shfl_xor_sync(0xffffffffu, s, o);
        q += __shfl_xor_sync(0xffffffffu, q, o);
    }
    if (lane == 0) { red[0][wid] = s; red[1][wid] = q; }
    __syncthreads();
    if (wid == 0) {
        s = (lane < 8) ? red[0][lane] : 0.f;
        q = (lane < 8) ? red[1][lane] : 0.f;
#pragma unroll
        for (int o = 4; o; o >>= 1) {
            s += __shfl_xor_sync(0xffffffffu, s, o);
            q += __shfl_xor_sync(0xffffffffu, q, o);
        }
        if (lane == 0) { red[0][0] = s; red[1][0] = q; }
    }
    __syncthreads();
    float mu  = red[0][0] * (1.f / Hh);
    float var = red[1][0] * (1.f / Hh) - mu * mu;
    float rstd = rsqrtf(var + 1e-5f);
    float4 wv = ((const float4*)w)[tid];
    float4 bb = ((const float4*)bv)[tid];
    float4 y;
    y.x = (v.x - mu) * rstd * wv.x + bb.x;
    y.y = (v.y - mu) * rstd * wv.y + bb.y;
    y.z = (v.z - mu) * rstd * wv.z + bb.z;
    y.w = (v.w - mu) * rstd * wv.w + bb.w;
    ((float4*)(Y + (size_t)row * Hh))[tid] = y;
}

// ---------------- driver ----------------
extern "C" void kernel_launch(void* const* d_in, const int* in_sizes, int n_in,
                              void* d_out, int out_size)
{
    const float* bone  = (const float*)d_in[0];
    const float* W_ih0 = (const float*)d_in[1];
    const float* W_hh0 = (const float*)d_in[2];
    const float* b_ih0 = (const float*)d_in[3];
    const float* b_hh0 = (const float*)d_in[4];
    const float* W_ih1 = (const float*)d_in[5];
    const float* W_hh1 = (const float*)d_in[6];
    const float* b_ih1 = (const float*)d_in[7];
    const float* b_hh1 = (const float*)d_in[8];
    const float* ln1w  = (const float*)d_in[9];
    const float* ln1b  = (const float*)d_in[10];
    const float* linw  = (const float*)d_in[11];
    const float* linb  = (const float*)d_in[12];
    const float* ln2w  = (const float*)d_in[13];
    const float* ln2b  = (const float*)d_in[14];
    float* out = (float*)d_out;

    float *xg = nullptr, *hseq = nullptr;
    __half *hseq16 = nullptr, *act16 = nullptr;
    __half *w16ih0 = nullptr, *w16ih1 = nullptr, *w16lin = nullptr;
    unsigned *wf0 = nullptr, *wf1 = nullptr;
    cudaGetSymbolAddress((void**)&xg, g_xg);
    cudaGetSymbolAddress((void**)&hseq, g_hseq);
    cudaGetSymbolAddress((void**)&hseq16, g_hseq16);
    cudaGetSymbolAddress((void**)&act16, g_act16);
    cudaGetSymbolAddress((void**)&wf0, g_wf0);
    cudaGetSymbolAddress((void**)&wf1, g_wf1);
    cudaGetSymbolAddress((void**)&w16ih0, g_w16ih0);
    cudaGetSymbolAddress((void**)&w16ih1, g_w16ih1);
    cudaGetSymbolAddress((void**)&w16lin, g_w16lin);
    float* lin = xg + (size_t)BT * Hh;   // reuse xg region after gates consumed

    cudaFuncSetAttribute(lstm_scan<__half>, cudaFuncAttributeMaxDynamicSharedMemorySize, SCAN_SMEM);
    cudaFuncSetAttribute(lstm_scan<float>,  cudaFuncAttributeMaxDynamicSharedMemorySize, SCAN_SMEM);

    dim3 gemm_g4(G4/128, BT/128);
    dim3 gemm_h(Hh/128, BT/128);

    // merged weight preps (2 launches)
    prep_whh_f16_2<<<16384, 256>>>(W_hh0, wf0, W_hh1, wf1);
    prep_w16_all<<<(N2_IH0 + N2_IH1 + N2_LIN + 255)/256, 256>>>(
        W_ih0, w16ih0, W_ih1, w16ih1, linw, w16lin);

    // layer 0: gates from fp32 input; scan writes fp16 hseq
    gemm_f16_nt_bias<float><<<gemm_g4, 256>>>(bone, w16ih0, b_ih0, b_hh0, xg, BT, G4, Dd);
    reset_scan_state<<<64, 256>>>();
    lstm_scan<__half><<<NCTA, 256, SCAN_SMEM>>>(wf0, xg, hseq16);

    // layer 1: gates from fp16 hseq; scan writes fp32 hseq
    gemm_f16_nt_bias<__half><<<gemm_g4, 256>>>(hseq16, w16ih1, b_ih1, b_hh1, xg, BT, G4, Hh);
    reset_scan_state<<<64, 256>>>();
    lstm_scan<float><<<NCTA, 256, SCAN_SMEM>>>(wf1, xg, hseq);

    // post: LN -> GELU (fp16) -> Linear (half-A) -> GELU -> LN
    ln_gelu_kernel<<<BT, 256>>>(hseq, ln1w, ln1b, act16);
    gemm_f16_nt_bias<__half><<<gemm_h, 256>>>(act16, w16lin, linb, nullptr, lin, BT, Hh, Hh);
    gelu_ln_kernel<<<BT, 256>>>(lin, ln2w, ln2b, out);
}